// round 2
// baseline (speedup 1.0000x reference)
#include <cuda_runtime.h>

#define M_ROWS 65536
#define N_COLS 640
#define K_DIM  512
#define GROUPS 2
#define NUM_VARS 320
#define CB_DIM 128
#define EPSV 1e-7f
#define NEG_HUGE -3.402823466e38f

// Scratch (static __device__ allocation only — no cudaMalloc allowed)
__device__ float        g_logits[(size_t)M_ROWS * N_COLS];
__device__ float        g_probsum[N_COLS];
__device__ unsigned int g_counts[N_COLS];

// ---------------------------------------------------------------------------
// Zero the cross-block accumulators (graph is replayed; must reset each call)
// ---------------------------------------------------------------------------
__global__ void zero_kernel() {
    int i = threadIdx.x;
    if (i < N_COLS) { g_probsum[i] = 0.0f; g_counts[i] = 0u; }
}

// ---------------------------------------------------------------------------
// Kernel 1: fp32 SIMT GEMM, 128x128 block tile, 8x8 per thread, BK=8,
// register-prefetch software pipeline. logits = x @ W + b -> g_logits
// ---------------------------------------------------------------------------
__global__ __launch_bounds__(256, 2)
void gemm_kernel(const float* __restrict__ A,     // x  [65536, 512]
                 const float* __restrict__ W,     // W  [512, 640]
                 const float* __restrict__ bias)  // b  [640]
{
    __shared__ __align__(16) float As[8][132];   // transposed: As[k][m], padded
    __shared__ __align__(16) float Bs[8][132];   // Bs[k][n], padded

    const int tid = threadIdx.x;
    const int bm  = blockIdx.y * 128;
    const int bn  = blockIdx.x * 128;
    const int ty  = tid >> 4;     // 0..15 -> row group
    const int tx  = tid & 15;     // 0..15 -> col group

    // Global load mapping
    const int arow = tid >> 1;            // 0..127
    const int acol = (tid & 1) << 2;      // 0 or 4
    const int brow = tid >> 5;            // 0..7
    const int bcol = (tid & 31) << 2;     // 0..124

    const float* Ap = A + (size_t)(bm + arow) * K_DIM + acol;
    const float* Bp = W + (size_t)brow * N_COLS + bn + bcol;

    float acc[8][8];
#pragma unroll
    for (int i = 0; i < 8; i++)
#pragma unroll
        for (int j = 0; j < 8; j++) acc[i][j] = 0.0f;

    float4 aReg = *(const float4*)Ap;
    float4 bReg = *(const float4*)Bp;

    for (int k0 = 0; k0 < K_DIM; k0 += 8) {
        // commit prefetched tile to smem
        As[acol + 0][arow] = aReg.x;
        As[acol + 1][arow] = aReg.y;
        As[acol + 2][arow] = aReg.z;
        As[acol + 3][arow] = aReg.w;
        *(float4*)&Bs[brow][bcol] = bReg;
        __syncthreads();

        if (k0 + 8 < K_DIM) {
            aReg = *(const float4*)(Ap + k0 + 8);
            bReg = *(const float4*)(Bp + (size_t)(k0 + 8) * N_COLS);
        }

#pragma unroll
        for (int kk = 0; kk < 8; kk++) {
            float4 a0 = *(const float4*)&As[kk][ty * 8];
            float4 a1 = *(const float4*)&As[kk][ty * 8 + 4];
            float4 b0 = *(const float4*)&Bs[kk][tx * 8];
            float4 b1 = *(const float4*)&Bs[kk][tx * 8 + 4];
            float a[8] = {a0.x, a0.y, a0.z, a0.w, a1.x, a1.y, a1.z, a1.w};
            float b[8] = {b0.x, b0.y, b0.z, b0.w, b1.x, b1.y, b1.z, b1.w};
#pragma unroll
            for (int i = 0; i < 8; i++)
#pragma unroll
                for (int j = 0; j < 8; j++)
                    acc[i][j] = fmaf(a[i], b[j], acc[i][j]);
        }
        __syncthreads();
    }

    // epilogue: add bias, write logits
    float bsv[8];
#pragma unroll
    for (int j = 0; j < 8; j++) bsv[j] = __ldg(&bias[bn + tx * 8 + j]);

#pragma unroll
    for (int i = 0; i < 8; i++) {
        float* cp = g_logits + (size_t)(bm + ty * 8 + i) * N_COLS + bn + tx * 8;
        float4 v0 = make_float4(acc[i][0] + bsv[0], acc[i][1] + bsv[1],
                                acc[i][2] + bsv[2], acc[i][3] + bsv[3]);
        float4 v1 = make_float4(acc[i][4] + bsv[4], acc[i][5] + bsv[5],
                                acc[i][6] + bsv[6], acc[i][7] + bsv[7]);
        *(float4*)cp       = v0;
        *(float4*)(cp + 4) = v1;
    }
}

// ---------------------------------------------------------------------------
// Kernel 2: per-row argmax + softmax accumulation + codebook gather.
// Each block owns 32 rows (4 batches of 8). Softmax-prob sums are accumulated
// in per-thread registers by column ownership (no smem atomic contention),
// flushed once per block with global atomics (2048 blocks * ~3 atomics/thread).
// ---------------------------------------------------------------------------
#define RPB   32
#define BATCH 8

__global__ __launch_bounds__(256)
void reduce_kernel(const float* __restrict__ codebook,   // [640, 128]
                   float* __restrict__ out)               // [65536, 256]
{
    __shared__ __align__(16) float sl[BATCH][N_COLS];
    __shared__ float sm[BATCH][2];
    __shared__ float sinv[BATCH][2];
    __shared__ int   sk[BATCH][2];
    __shared__ unsigned int shist[N_COLS];

    const int tid  = threadIdx.x;
    const int lane = tid & 31;
    const int warp = tid >> 5;

    for (int i = tid; i < N_COLS; i += 256) shist[i] = 0u;

    // column ownership: c0 in [0,256) (group 0), c1 in [256,512) (mixed),
    // c2 in [512,640) (group 1, only for tid<128)
    const int c0 = tid, c1 = tid + 256, c2 = tid + 512;
    float accp0 = 0.0f, accp1 = 0.0f, accp2 = 0.0f;
    const bool c1g0 = (c1 < NUM_VARS);  // always false here (c1>=256<320? no: 256<320 true for tid<64)

    const int row0 = blockIdx.x * RPB;

    for (int rb = 0; rb < RPB; rb += BATCH) {
        const int rbase = row0 + rb;
        __syncthreads();   // protect smem reuse across batches

        // load 8x640 logits (contiguous) into smem
        const float4* src = (const float4*)(g_logits + (size_t)rbase * N_COLS);
        float4* dst = (float4*)&sl[0][0];
#pragma unroll
        for (int i = 0; i < (BATCH * N_COLS) / 4 / 256; i++)
            dst[tid + i * 256] = src[tid + i * 256];
        __syncthreads();

        // warp w reduces row w: per group max/argmax (first-max tiebreak) + sumexp
        if (warp < BATCH) {
            const int r = warp;
#pragma unroll
            for (int g = 0; g < GROUPS; g++) {
                const float* lp = &sl[r][g * NUM_VARS];
                float bv = NEG_HUGE; int bi = 0;
#pragma unroll
                for (int j = 0; j < NUM_VARS / 32; j++) {
                    int idx = lane + 32 * j;
                    float v = lp[idx];
                    if (v > bv) { bv = v; bi = idx; }
                }
#pragma unroll
                for (int s = 16; s > 0; s >>= 1) {
                    float ov = __shfl_xor_sync(0xffffffffu, bv, s);
                    int   oi = __shfl_xor_sync(0xffffffffu, bi, s);
                    if (ov > bv || (ov == bv && oi < bi)) { bv = ov; bi = oi; }
                }
                float se = 0.0f;
#pragma unroll
                for (int j = 0; j < NUM_VARS / 32; j++)
                    se += __expf(lp[lane + 32 * j] - bv);
#pragma unroll
                for (int s = 16; s > 0; s >>= 1)
                    se += __shfl_xor_sync(0xffffffffu, se, s);
                if (lane == 0) {
                    sm[r][g]   = bv;
                    sinv[r][g] = 1.0f / se;
                    sk[r][g]   = bi;
                    atomicAdd(&shist[g * NUM_VARS + bi], 1u);
                }
            }
        }
        __syncthreads();

        // softmax-prob accumulation by column owner (register accumulators)
#pragma unroll
        for (int r = 0; r < BATCH; r++) {
            float m0 = sm[r][0], m1 = sm[r][1];
            float i0 = sinv[r][0], i1 = sinv[r][1];
            accp0 += __expf(sl[r][c0] - m0) * i0;                       // c0 < 256 < 320
            if (c1g0) accp1 += __expf(sl[r][c1] - m0) * i0;
            else      accp1 += __expf(sl[r][c1] - m1) * i1;
            if (c2 < N_COLS) accp2 += __expf(sl[r][c2] - m1) * i1;      // c2 >= 512
        }

        // gather epilogue: 256 output floats per row, one per thread
#pragma unroll
        for (int r = 0; r < BATCH; r++) {
            const int row = rbase + r;
            const int c   = tid;            // 0..255
            const int g   = c >> 7;         // 0 or 1
            const int k   = sk[r][g];
            out[(size_t)row * 256 + c] =
                __ldg(&codebook[(size_t)(g * NUM_VARS + k) * CB_DIM + (c & 127)]);
        }
    }

    // flush block-local accumulators
    __syncthreads();
    atomicAdd(&g_probsum[c0], accp0);
    atomicAdd(&g_probsum[c1], accp1);
    if (c2 < N_COLS) atomicAdd(&g_probsum[c2], accp2);
    for (int i = tid; i < N_COLS; i += 256)
        if (shist[i]) atomicAdd(&g_counts[i], shist[i]);
}

// ---------------------------------------------------------------------------
// Kernel 3: perplexities from the accumulated sums (tiny)
// ---------------------------------------------------------------------------
__global__ void finalize_kernel(float* __restrict__ out2)  // points at last 2 floats
{
    __shared__ float red_h[N_COLS];
    __shared__ float red_s[N_COLS];
    __shared__ float gh[2], gs[2];
    const int tid = threadIdx.x;   // 640 threads
    const float invN = 1.0f / (float)M_ROWS;

    if (tid < N_COLS) {
        float ph = (float)g_counts[tid] * invN;
        float ps = g_probsum[tid] * invN;
        red_h[tid] = ph * logf(ph + EPSV);
        red_s[tid] = ps * logf(ps + EPSV);
    }
    __syncthreads();

    if (tid < 64) {
        const int g = tid >> 5, lane = tid & 31;
        float sh = 0.0f, ss = 0.0f;
#pragma unroll
        for (int j = 0; j < NUM_VARS / 32; j++) {
            sh += red_h[g * NUM_VARS + lane + 32 * j];
            ss += red_s[g * NUM_VARS + lane + 32 * j];
        }
#pragma unroll
        for (int s = 16; s > 0; s >>= 1) {
            sh += __shfl_xor_sync(0xffffffffu, sh, s);
            ss += __shfl_xor_sync(0xffffffffu, ss, s);
        }
        if (lane == 0) { gh[g] = expf(-sh); gs[g] = expf(-ss); }
    }
    __syncthreads();

    if (tid == 0) {
        out2[0] = gh[0] + gh[1];   // code_perplexity
        out2[1] = gs[0] + gs[1];   // prob_perplexity
    }
}

// ---------------------------------------------------------------------------
extern "C" void kernel_launch(void* const* d_in, const int* in_sizes, int n_in,
                              void* d_out, int out_size)
{
    const float* x    = (const float*)d_in[0];   // [16,4096,512]
    const float* W    = (const float*)d_in[1];   // [512,640]
    const float* b    = (const float*)d_in[2];   // [640]
    const float* cb   = (const float*)d_in[3];   // [640,128]
    float*       out  = (float*)d_out;           // [16*4096*256] ++ [2]

    zero_kernel<<<1, N_COLS>>>();

    dim3 gg(N_COLS / 128, M_ROWS / 128);   // (5, 512)
    gemm_kernel<<<gg, 256>>>(x, W, b);

    reduce_kernel<<<M_ROWS / RPB, 256>>>(cb, out);

    finalize_kernel<<<1, N_COLS>>>(out + out_size - 2);
}

// round 4
// speedup vs baseline: 1.0265x; 1.0265x over previous
#include <cuda_runtime.h>
#include <cstdint>

#define M_ROWS 65536
#define N_COLS 640
#define K_DIM  512
#define GROUPS 2
#define NUM_VARS 320
#define CB_DIM 128
#define EPSV 1e-7f
#define NEG_HUGE -3.402823466e38f
#define GAP_THR 0.05f

// ---------------------------------------------------------------------------
// Static device scratch (no cudaMalloc allowed)
// ---------------------------------------------------------------------------
__device__ float        g_logits[(size_t)M_ROWS * N_COLS];
__device__ float        g_wt[(size_t)N_COLS * K_DIM];      // W^T (fp32), for exact recheck
__device__ float        g_probsum[N_COLS];
__device__ unsigned int g_counts[N_COLS];

// ---------------------------------------------------------------------------
// Helpers (baseline sm_103 PTX only: cp.async, mma.sync, cvt.rna.tf32)
// ---------------------------------------------------------------------------
__device__ __forceinline__ uint32_t smem_to_u32(const void* p) {
    uint32_t a;
    asm("{ .reg .u64 t; cvta.to.shared.u64 t, %1; cvt.u32.u64 %0, t; }" : "=r"(a) : "l"(p));
    return a;
}
__device__ __forceinline__ void cp16(uint32_t s, const void* g) {
    asm volatile("cp.async.cg.shared.global [%0], [%1], 16;" :: "r"(s), "l"(g) : "memory");
}
__device__ __forceinline__ void cp_commit() {
    asm volatile("cp.async.commit_group;" ::: "memory");
}
__device__ __forceinline__ void tf32split(float v, uint32_t& hi, uint32_t& lo) {
    asm("cvt.rna.tf32.f32 %0, %1;" : "=r"(hi) : "f"(v));
    float l = v - __uint_as_float(hi);
    asm("cvt.rna.tf32.f32 %0, %1;" : "=r"(lo) : "f"(l));
}
__device__ __forceinline__ void mma_tf32(float* c, const uint32_t* a, const uint32_t* b) {
    asm volatile(
        "mma.sync.aligned.m16n8k8.row.col.f32.tf32.tf32.f32 "
        "{%0,%1,%2,%3}, {%4,%5,%6,%7}, {%8,%9}, {%0,%1,%2,%3};"
        : "+f"(c[0]), "+f"(c[1]), "+f"(c[2]), "+f"(c[3])
        : "r"(a[0]), "r"(a[1]), "r"(a[2]), "r"(a[3]), "r"(b[0]), "r"(b[1]));
}

// ---------------------------------------------------------------------------
// Kernel 0a: zero accumulators (graph replayed -> reset every call)
// ---------------------------------------------------------------------------
__global__ void zero_kernel() {
    int i = threadIdx.x;
    if (i < N_COLS) { g_probsum[i] = 0.0f; g_counts[i] = 0u; }
}

// ---------------------------------------------------------------------------
// Kernel 0b: plain W transpose (for the exact argmax recheck path)
// ---------------------------------------------------------------------------
__global__ void wtrans_kernel(const float* __restrict__ W) {
    int i = blockIdx.x * 256 + threadIdx.x;
    if (i < K_DIM * N_COLS) {
        int k = i / N_COLS, n = i % N_COLS;
        g_wt[(size_t)n * K_DIM + k] = W[i];
    }
}

// ---------------------------------------------------------------------------
// Kernel 1: tf32x3 GEMM via mma.sync.m16n8k8 (register accumulators).
// CTA tile 128x128, 8 warps (warp tile 32x64), K-chunks of 32 fp32,
// cp.async double buffering, in-register tf32 hi/lo split.
//   smem A: [128][36] fp32 (pad 4 -> frag LDS conflict-free)
//   smem B: [32][136] fp32 (pad 8 -> frag LDS conflict-free), B = W rows k, cols n
// ---------------------------------------------------------------------------
#define A_STRIDE 36
#define B_STRIDE 136
#define A_BYTES  (128 * A_STRIDE * 4)    // 18432
#define B_BYTES  (32 * B_STRIDE * 4)     // 17408
#define STAGE_BYTES (A_BYTES + B_BYTES)  // 35840
#define GEMM_SMEM   (2 * STAGE_BYTES)    // 71680
#define NCHUNK 16

__global__ __launch_bounds__(256, 1)
void gemm_mma_kernel(const float* __restrict__ A,     // x [65536, 512]
                     const float* __restrict__ Wp,    // W [512, 640]
                     const float* __restrict__ bias)  // b [640]
{
    extern __shared__ char smem[];
    const int tid  = threadIdx.x;
    const int wid  = tid >> 5;
    const int lane = tid & 31;
    const int bm   = blockIdx.y * 128;
    const int bn   = blockIdx.x * 128;
    const int wm   = wid & 3;      // M-warp 0..3 -> rows wm*32..+32
    const int wn   = wid >> 2;     // N-warp 0..1 -> cols wn*64..+64
    const int grp  = lane >> 2;    // 0..7
    const int tg   = lane & 3;     // 0..3
    const uint32_t sb = smem_to_u32(smem);

    float acc[2][8][4];
#pragma unroll
    for (int mf = 0; mf < 2; mf++)
#pragma unroll
        for (int nf = 0; nf < 8; nf++)
#pragma unroll
            for (int r = 0; r < 4; r++) acc[mf][nf][r] = 0.0f;

    // ---- gmem -> smem loader (cp.async), one K-chunk of 32 ----
    const int am = tid >> 1, ao = (tid & 1) * 16;   // A: row, 16-float half
    const int bk = tid >> 3, bo = (tid & 7) * 16;   // B: k-row, 16-float piece
    const float* Ag = A  + (size_t)(bm + am) * K_DIM + ao;
    const float* Bg = Wp + (size_t)bk * N_COLS + bn + bo;
    const uint32_t AsBase = (uint32_t)(am * A_STRIDE + ao) * 4;
    const uint32_t BsBase = (uint32_t)(bk * B_STRIDE + bo) * 4;

#define LOAD_CHUNK(c, st) do {                                                  \
        uint32_t _sA = sb + (uint32_t)(st) * STAGE_BYTES + AsBase;              \
        const float* _ga = Ag + (c) * 32;                                       \
        cp16(_sA,      _ga);     cp16(_sA + 16, _ga + 4);                       \
        cp16(_sA + 32, _ga + 8); cp16(_sA + 48, _ga + 12);                      \
        uint32_t _sB = sb + (uint32_t)(st) * STAGE_BYTES + A_BYTES + BsBase;    \
        const float* _gb = Bg + (size_t)(c) * 32 * N_COLS;                      \
        cp16(_sB,      _gb);     cp16(_sB + 16, _gb + 4);                       \
        cp16(_sB + 32, _gb + 8); cp16(_sB + 48, _gb + 12);                      \
        cp_commit();                                                            \
    } while (0)

    LOAD_CHUNK(0, 0);

    for (int c = 0; c < NCHUNK; c++) {
        const int st = c & 1;
        if (c + 1 < NCHUNK) {
            LOAD_CHUNK(c + 1, (c + 1) & 1);
            asm volatile("cp.async.wait_group 1;" ::: "memory");
        } else {
            asm volatile("cp.async.wait_group 0;" ::: "memory");
        }
        __syncthreads();

        const float* As = (const float*)(smem + (size_t)st * STAGE_BYTES);
        const float* Bs = (const float*)(smem + (size_t)st * STAGE_BYTES + A_BYTES);

#pragma unroll
        for (int ks = 0; ks < 4; ks++) {
            const int k0 = ks * 8;
            // A fragments (hi/lo) for 2 m-frags
            uint32_t ah[2][4], al[2][4];
#pragma unroll
            for (int mf = 0; mf < 2; mf++) {
                const int mr = wm * 32 + mf * 16 + grp;
                tf32split(As[(mr)     * A_STRIDE + k0 + tg],     ah[mf][0], al[mf][0]);
                tf32split(As[(mr + 8) * A_STRIDE + k0 + tg],     ah[mf][1], al[mf][1]);
                tf32split(As[(mr)     * A_STRIDE + k0 + tg + 4], ah[mf][2], al[mf][2]);
                tf32split(As[(mr + 8) * A_STRIDE + k0 + tg + 4], ah[mf][3], al[mf][3]);
            }
            // B fragments (hi/lo) for 8 n-frags
            uint32_t bh[8][2], bl[8][2];
#pragma unroll
            for (int nf = 0; nf < 8; nf++) {
                const int nc = wn * 64 + nf * 8 + grp;
                tf32split(Bs[(k0 + tg)     * B_STRIDE + nc], bh[nf][0], bl[nf][0]);
                tf32split(Bs[(k0 + tg + 4) * B_STRIDE + nc], bh[nf][1], bl[nf][1]);
            }
#pragma unroll
            for (int mf = 0; mf < 2; mf++)
#pragma unroll
                for (int nf = 0; nf < 8; nf++) {
                    mma_tf32(acc[mf][nf], ah[mf], bh[nf]);
                    mma_tf32(acc[mf][nf], al[mf], bh[nf]);
                    mma_tf32(acc[mf][nf], ah[mf], bl[nf]);
                }
        }
        __syncthreads();
    }

    // ---- epilogue: bias add, store logits ----
#pragma unroll
    for (int mf = 0; mf < 2; mf++) {
        const int row = bm + wm * 32 + mf * 16 + grp;
#pragma unroll
        for (int nf = 0; nf < 8; nf++) {
            const int col = bn + wn * 64 + nf * 8 + tg * 2;
            const float b0 = __ldg(&bias[col]);
            const float b1 = __ldg(&bias[col + 1]);
            float2 v0 = make_float2(acc[mf][nf][0] + b0, acc[mf][nf][1] + b1);
            float2 v1 = make_float2(acc[mf][nf][2] + b0, acc[mf][nf][3] + b1);
            *(float2*)&g_logits[(size_t)row * N_COLS + col]       = v0;
            *(float2*)&g_logits[(size_t)(row + 8) * N_COLS + col] = v1;
        }
    }
}

// ---------------------------------------------------------------------------
// Kernel 2: per-row argmax (top-2 + exact fp32 recheck on near-ties) +
// softmax accumulation + codebook gather.
// ---------------------------------------------------------------------------
#define RPB   32
#define BATCH 8

__global__ __launch_bounds__(256)
void reduce_kernel(const float* __restrict__ codebook,   // [640, 128]
                   const float* __restrict__ x,          // [65536, 512]
                   const float* __restrict__ bias,       // [640]
                   float* __restrict__ out)              // [65536, 256]
{
    __shared__ __align__(16) float sl[BATCH][N_COLS];
    __shared__ float sm[BATCH][2];
    __shared__ float sinv[BATCH][2];
    __shared__ int   sk[BATCH][2];
    __shared__ unsigned int shist[N_COLS];

    const int tid  = threadIdx.x;
    const int lane = tid & 31;
    const int warp = tid >> 5;

    for (int i = tid; i < N_COLS; i += 256) shist[i] = 0u;

    const int c0 = tid, c1 = tid + 256, c2 = tid + 512;
    float accp0 = 0.0f, accp1 = 0.0f, accp2 = 0.0f;
    const bool c1g0 = (c1 < NUM_VARS);

    const int row0 = blockIdx.x * RPB;

    for (int rb = 0; rb < RPB; rb += BATCH) {
        const int rbase = row0 + rb;
        __syncthreads();

        const float4* src = (const float4*)(g_logits + (size_t)rbase * N_COLS);
        float4* dst = (float4*)&sl[0][0];
#pragma unroll
        for (int i = 0; i < (BATCH * N_COLS) / 4 / 256; i++)
            dst[tid + i * 256] = src[tid + i * 256];
        __syncthreads();

        if (warp < BATCH) {
            const int r = warp;
            const int row = rbase + r;
#pragma unroll
            for (int g = 0; g < GROUPS; g++) {
                const float* lp = &sl[r][g * NUM_VARS];
                // lane-local top-2
                float bv = NEG_HUGE, sv = NEG_HUGE;
                int   bi = 0,        si = 0;
#pragma unroll
                for (int j = 0; j < NUM_VARS / 32; j++) {
                    int idx = lane + 32 * j;
                    float v = lp[idx];
                    if (v > bv)      { sv = bv; si = bi; bv = v; bi = idx; }
                    else if (v > sv) { sv = v; si = idx; }
                }
                // warp butterfly top-2 merge
#pragma unroll
                for (int s = 16; s > 0; s >>= 1) {
                    float ob = __shfl_xor_sync(0xffffffffu, bv, s);
                    int   oi = __shfl_xor_sync(0xffffffffu, bi, s);
                    float os = __shfl_xor_sync(0xffffffffu, sv, s);
                    int   oj = __shfl_xor_sync(0xffffffffu, si, s);
                    if (ob > bv || (ob == bv && oi < bi)) {
                        // other's top wins; new second = max(my top, other's second)
                        if (os > bv || (os == bv && oj < bi)) { sv = os; si = oj; }
                        else                                  { sv = bv; si = bi; }
                        bv = ob; bi = oi;
                    } else {
                        if (ob > sv || (ob == sv && oi < si)) { sv = ob; si = oi; }
                    }
                }
                // near-tie -> exact fp32 recheck of the two candidates
                if (bv - sv < GAP_THR) {
                    const float* xr = x + (size_t)row * K_DIM;
                    const float* w1 = g_wt + (size_t)(g * NUM_VARS + bi) * K_DIM;
                    const float* w2 = g_wt + (size_t)(g * NUM_VARS + si) * K_DIM;
                    float d1 = 0.0f, d2 = 0.0f;
#pragma unroll
                    for (int k = lane; k < K_DIM; k += 32) {
                        float xv = xr[k];
                        d1 = fmaf(xv, w1[k], d1);
                        d2 = fmaf(xv, w2[k], d2);
                    }
#pragma unroll
                    for (int s = 16; s > 0; s >>= 1) {
                        d1 += __shfl_xor_sync(0xffffffffu, d1, s);
                        d2 += __shfl_xor_sync(0xffffffffu, d2, s);
                    }
                    d1 += bias[g * NUM_VARS + bi];
                    d2 += bias[g * NUM_VARS + si];
                    if (d2 > d1 || (d2 == d1 && si < bi)) bi = si;
                }
                // softmax denominator (uses approx max; stability only)
                float se = 0.0f;
#pragma unroll
                for (int j = 0; j < NUM_VARS / 32; j++)
                    se += __expf(lp[lane + 32 * j] - bv);
#pragma unroll
                for (int s = 16; s > 0; s >>= 1)
                    se += __shfl_xor_sync(0xffffffffu, se, s);
                if (lane == 0) {
                    sm[r][g]   = bv;
                    sinv[r][g] = 1.0f / se;
                    sk[r][g]   = bi;
                    atomicAdd(&shist[g * NUM_VARS + bi], 1u);
                }
            }
        }
        __syncthreads();

#pragma unroll
        for (int r = 0; r < BATCH; r++) {
            float m0 = sm[r][0], m1 = sm[r][1];
            float i0 = sinv[r][0], i1 = sinv[r][1];
            accp0 += __expf(sl[r][c0] - m0) * i0;
            if (c1g0) accp1 += __expf(sl[r][c1] - m0) * i0;
            else      accp1 += __expf(sl[r][c1] - m1) * i1;
            if (c2 < N_COLS) accp2 += __expf(sl[r][c2] - m1) * i1;
        }

#pragma unroll
        for (int r = 0; r < BATCH; r++) {
            const int row = rbase + r;
            const int c   = tid;
            const int g   = c >> 7;
            const int k   = sk[r][g];
            out[(size_t)row * 256 + c] =
                __ldg(&codebook[(size_t)(g * NUM_VARS + k) * CB_DIM + (c & 127)]);
        }
    }

    __syncthreads();
    atomicAdd(&g_probsum[c0], accp0);
    atomicAdd(&g_probsum[c1], accp1);
    if (c2 < N_COLS) atomicAdd(&g_probsum[c2], accp2);
    for (int i = tid; i < N_COLS; i += 256)
        if (shist[i]) atomicAdd(&g_counts[i], shist[i]);
}

// ---------------------------------------------------------------------------
// Kernel 3: perplexities (tiny)
// ---------------------------------------------------------------------------
__global__ void finalize_kernel(float* __restrict__ out2)
{
    __shared__ float red_h[N_COLS];
    __shared__ float red_s[N_COLS];
    __shared__ float gh[2], gs[2];
    const int tid = threadIdx.x;
    const float invN = 1.0f / (float)M_ROWS;

    if (tid < N_COLS) {
        float ph = (float)g_counts[tid] * invN;
        float ps = g_probsum[tid] * invN;
        red_h[tid] = ph * logf(ph + EPSV);
        red_s[tid] = ps * logf(ps + EPSV);
    }
    __syncthreads();

    if (tid < 64) {
        const int g = tid >> 5, lane = tid & 31;
        float sh = 0.0f, ss = 0.0f;
#pragma unroll
        for (int j = 0; j < NUM_VARS / 32; j++) {
            sh += red_h[g * NUM_VARS + lane + 32 * j];
            ss += red_s[g * NUM_VARS + lane + 32 * j];
        }
#pragma unroll
        for (int s = 16; s > 0; s >>= 1) {
            sh += __shfl_xor_sync(0xffffffffu, sh, s);
            ss += __shfl_xor_sync(0xffffffffu, ss, s);
        }
        if (lane == 0) { gh[g] = expf(-sh); gs[g] = expf(-ss); }
    }
    __syncthreads();

    if (tid == 0) {
        out2[0] = gh[0] + gh[1];
        out2[1] = gs[0] + gs[1];
    }
}

// ---------------------------------------------------------------------------
extern "C" void kernel_launch(void* const* d_in, const int* in_sizes, int n_in,
                              void* d_out, int out_size)
{
    const float* x   = (const float*)d_in[0];   // [16,4096,512]
    const float* W   = (const float*)d_in[1];   // [512,640]
    const float* b   = (const float*)d_in[2];   // [640]
    const float* cb  = (const float*)d_in[3];   // [640,128]
    float*       out = (float*)d_out;

    cudaFuncSetAttribute(gemm_mma_kernel,
                         cudaFuncAttributeMaxDynamicSharedMemorySize, GEMM_SMEM);

    zero_kernel<<<1, N_COLS>>>();
    wtrans_kernel<<<(K_DIM * N_COLS + 255) / 256, 256>>>(W);

    dim3 gg(N_COLS / 128, M_ROWS / 128);   // (5, 512)
    gemm_mma_kernel<<<gg, 256, GEMM_SMEM>>>(x, W, b);

    reduce_kernel<<<M_ROWS / RPB, 256>>>(cb, x, b, out);

    finalize_kernel<<<1, N_COLS>>>(out + out_size - 2);
}

// round 5
// speedup vs baseline: 1.6349x; 1.5927x over previous
#include <cuda_runtime.h>
#include <cstdint>

#define M_ROWS 65536
#define N_COLS 640
#define K_DIM  512
#define GROUPS 2
#define NUM_VARS 320
#define CB_DIM 128
#define EPSV 1e-7f
#define NEG_HUGE -3.402823466e38f
#define GAP_THR 0.05f

// ---------------------------------------------------------------------------
// Static device scratch (no cudaMalloc allowed)
// ---------------------------------------------------------------------------
__device__ float        g_logits[(size_t)M_ROWS * N_COLS];
__device__ float        g_wt[(size_t)N_COLS * K_DIM];            // W^T fp32 (exact recheck)
__device__ uint32_t     g_wtb_hi[(size_t)N_COLS * (K_DIM / 2)];  // W^T bf16-hi, k-pair packed
__device__ uint32_t     g_wtb_mid[(size_t)N_COLS * (K_DIM / 2)]; // W^T bf16-mid residual
__device__ float        g_probsum[N_COLS];
__device__ unsigned int g_counts[N_COLS];

// ---------------------------------------------------------------------------
// Helpers (baseline sm_103 PTX only: cp.async, mma.sync bf16, cvt.rn.bf16x2)
// ---------------------------------------------------------------------------
__device__ __forceinline__ uint32_t smem_to_u32(const void* p) {
    uint32_t a;
    asm("{ .reg .u64 t; cvta.to.shared.u64 t, %1; cvt.u32.u64 %0, t; }" : "=r"(a) : "l"(p));
    return a;
}
__device__ __forceinline__ void cp16(uint32_t s, const void* g) {
    asm volatile("cp.async.cg.shared.global [%0], [%1], 16;" :: "r"(s), "l"(g) : "memory");
}
__device__ __forceinline__ void cp_commit() {
    asm volatile("cp.async.commit_group;" ::: "memory");
}
// split two consecutive-k floats (e = k even, o = k odd) into packed bf16x2
// hi word + bf16x2 mid (residual) word.  d.hi = first PTX src, d.lo = second.
__device__ __forceinline__ void bsplit2(float e, float o, uint32_t& hi, uint32_t& mid) {
    uint32_t h;
    asm("cvt.rn.bf16x2.f32 %0, %1, %2;" : "=r"(h) : "f"(o), "f"(e));
    float he = __uint_as_float(h << 16);
    float ho = __uint_as_float(h & 0xffff0000u);
    asm("cvt.rn.bf16x2.f32 %0, %1, %2;" : "=r"(mid) : "f"(o - ho), "f"(e - he));
    hi = h;
}
__device__ __forceinline__ void mma_bf16(float* c, const uint32_t* a, const uint32_t* b) {
    asm volatile(
        "mma.sync.aligned.m16n8k16.row.col.f32.bf16.bf16.f32 "
        "{%0,%1,%2,%3}, {%4,%5,%6,%7}, {%8,%9}, {%0,%1,%2,%3};"
        : "+f"(c[0]), "+f"(c[1]), "+f"(c[2]), "+f"(c[3])
        : "r"(a[0]), "r"(a[1]), "r"(a[2]), "r"(a[3]), "r"(b[0]), "r"(b[1]));
}
#define STS128U(a0, a1, a2, a3, saddr) \
    asm volatile("st.shared.v4.b32 [%0], {%1, %2, %3, %4};" :: "r"(saddr), "r"(a0), "r"(a1), "r"(a2), "r"(a3) : "memory")

// ---------------------------------------------------------------------------
// Kernel 0a: zero accumulators (graph replayed -> reset every call)
// ---------------------------------------------------------------------------
__global__ void zero_kernel() {
    int i = threadIdx.x;
    if (i < N_COLS) { g_probsum[i] = 0.0f; g_counts[i] = 0u; }
}

// ---------------------------------------------------------------------------
// Kernel 0b: W prep — fp32 transpose (recheck) + bf16 hi/mid split, k-packed
// ---------------------------------------------------------------------------
__global__ __launch_bounds__(256)
void wprep_kernel(const float* __restrict__ W) {
    __shared__ float t[64][65];
    const int kt = blockIdx.x * 64, nt = blockIdx.y * 64;
    const int tid = threadIdx.x;

    for (int i = tid; i < 64 * 64; i += 256) {
        int k = i >> 6, n = i & 63;
        t[k][n] = W[(size_t)(kt + k) * N_COLS + nt + n];
    }
    __syncthreads();
    for (int i = tid; i < 64 * 64; i += 256) {
        int n = i >> 6, k = i & 63;
        g_wt[(size_t)(nt + n) * K_DIM + kt + k] = t[k][n];
    }
    for (int i = tid; i < 64 * 32; i += 256) {
        int n = i >> 5, w = i & 31;
        uint32_t hi, mid;
        bsplit2(t[2 * w][n], t[2 * w + 1][n], hi, mid);
        g_wtb_hi [(size_t)(nt + n) * (K_DIM / 2) + (kt >> 1) + w] = hi;
        g_wtb_mid[(size_t)(nt + n) * (K_DIM / 2) + (kt >> 1) + w] = mid;
    }
}

// ---------------------------------------------------------------------------
// Kernel 1: bf16x3 GEMM via mma.sync.m16n8k16.  CTA 128x128, 8 warps
// (warp tile 32x64), K-chunks of 32 fp32 (= 16 packed words), double-buffered:
// B hi/mid tiles via cp.async from pre-split g_wtb, A split in-register -> STS.
// Smem rows padded to 20 words -> all fragment LDS conflict-free.
// ---------------------------------------------------------------------------
#define SM_STRIDE 20
#define ATILE_B   (128 * SM_STRIDE * 4)   // 10240 bytes per tile
#define AHI_OFF   0
#define AMID_OFF  ATILE_B
#define BHI_OFF   (2 * ATILE_B)
#define BMID_OFF  (3 * ATILE_B)
#define STAGE_B   (4 * ATILE_B)           // 40960
#define GEMM_SMEM (2 * STAGE_B)           // 81920
#define NCHUNK 16

__global__ __launch_bounds__(256, 1)
void gemm_bf16x3_kernel(const float* __restrict__ A,     // x [65536, 512]
                        const float* __restrict__ bias)  // b [640]
{
    extern __shared__ char smem[];
    const int tid  = threadIdx.x;
    const int wid  = tid >> 5;
    const int lane = tid & 31;
    const int bm   = blockIdx.y * 128;
    const int bn   = blockIdx.x * 128;
    const int wm   = wid & 3;      // M-warp 0..3 -> rows wm*32..+32
    const int wn   = wid >> 2;     // N-warp 0..1 -> cols wn*64..+64
    const int grp  = lane >> 2;    // 0..7
    const int tg   = lane & 3;     // 0..3
    const uint32_t sb = smem_to_u32(smem);

    float acc[2][8][4];
#pragma unroll
    for (int mf = 0; mf < 2; mf++)
#pragma unroll
        for (int nf = 0; nf < 8; nf++)
#pragma unroll
            for (int r = 0; r < 4; r++) acc[mf][nf][r] = 0.0f;

    // loader mapping: thread -> (row 0..127, half 0/1 of the 32-float chunk)
    const int lr = tid >> 1;
    const int lh = tid & 1;
    const float4*   Ag  = (const float4*)(A + (size_t)(bm + lr) * K_DIM + lh * 16);
    const uint32_t* Bhg = g_wtb_hi  + (size_t)(bn + lr) * (K_DIM / 2) + lh * 8;
    const uint32_t* Bmg = g_wtb_mid + (size_t)(bn + lr) * (K_DIM / 2) + lh * 8;
    const uint32_t  aBase = (uint32_t)(lr * SM_STRIDE + lh * 8) * 4;

    float4 av[4];

    // split registers -> smem stage (hi + mid tiles)
#define STS_A(stg) do {                                                          \
        uint32_t _hw[8], _mw[8];                                                 \
        _Pragma("unroll")                                                        \
        for (int q = 0; q < 4; q++) {                                            \
            bsplit2(av[q].x, av[q].y, _hw[2*q],   _mw[2*q]);                     \
            bsplit2(av[q].z, av[q].w, _hw[2*q+1], _mw[2*q+1]);                   \
        }                                                                        \
        uint32_t _ba = sb + (uint32_t)(stg) * STAGE_B + aBase;                   \
        STS128U(_hw[0], _hw[1], _hw[2], _hw[3], _ba + AHI_OFF);                  \
        STS128U(_hw[4], _hw[5], _hw[6], _hw[7], _ba + AHI_OFF + 16);             \
        STS128U(_mw[0], _mw[1], _mw[2], _mw[3], _ba + AMID_OFF);                 \
        STS128U(_mw[4], _mw[5], _mw[6], _mw[7], _ba + AMID_OFF + 16);            \
    } while (0)

#define CP_B(c, stg) do {                                                        \
        uint32_t _bb = sb + (uint32_t)(stg) * STAGE_B + aBase;                   \
        const uint32_t* _gh = Bhg + (c) * 16;                                    \
        const uint32_t* _gm = Bmg + (c) * 16;                                    \
        cp16(_bb + BHI_OFF,       _gh);   cp16(_bb + BHI_OFF + 16,  _gh + 4);    \
        cp16(_bb + BMID_OFF,      _gm);   cp16(_bb + BMID_OFF + 16, _gm + 4);    \
        cp_commit();                                                             \
    } while (0)

    // prologue: chunk0 -> stage0; A(1) into regs
#pragma unroll
    for (int q = 0; q < 4; q++) av[q] = Ag[q];
    CP_B(0, 0);
    STS_A(0);
#pragma unroll
    for (int q = 0; q < 4; q++) av[q] = Ag[8 + q];

    for (int c = 0; c < NCHUNK; c++) {
        const int st = c & 1;
        if (c + 1 < NCHUNK) {
            STS_A(st ^ 1);                       // A(c+1) regs -> stage st^1
            if (c + 2 < NCHUNK) {
#pragma unroll
                for (int q = 0; q < 4; q++) av[q] = Ag[(c + 2) * 8 + q];
            }
            CP_B(c + 1, st ^ 1);
            asm volatile("cp.async.wait_group 1;" ::: "memory");
        } else {
            asm volatile("cp.async.wait_group 0;" ::: "memory");
        }
        __syncthreads();

        const uint32_t* Ah = (const uint32_t*)(smem + (size_t)st * STAGE_B + AHI_OFF);
        const uint32_t* Am = (const uint32_t*)(smem + (size_t)st * STAGE_B + AMID_OFF);
        const uint32_t* Bh = (const uint32_t*)(smem + (size_t)st * STAGE_B + BHI_OFF);
        const uint32_t* Bm = (const uint32_t*)(smem + (size_t)st * STAGE_B + BMID_OFF);

#pragma unroll
        for (int ks = 0; ks < 2; ks++) {
            const int w0 = ks * 8 + tg;
            uint32_t ahh[2][4], amm[2][4];
#pragma unroll
            for (int mf = 0; mf < 2; mf++) {
                const int r = wm * 32 + mf * 16 + grp;
                ahh[mf][0] = Ah[r * SM_STRIDE + w0];
                ahh[mf][1] = Ah[(r + 8) * SM_STRIDE + w0];
                ahh[mf][2] = Ah[r * SM_STRIDE + w0 + 4];
                ahh[mf][3] = Ah[(r + 8) * SM_STRIDE + w0 + 4];
                amm[mf][0] = Am[r * SM_STRIDE + w0];
                amm[mf][1] = Am[(r + 8) * SM_STRIDE + w0];
                amm[mf][2] = Am[r * SM_STRIDE + w0 + 4];
                amm[mf][3] = Am[(r + 8) * SM_STRIDE + w0 + 4];
            }
#pragma unroll
            for (int nf = 0; nf < 8; nf++) {
                const int nr = wn * 64 + nf * 8 + grp;
                uint32_t bhh[2], bmm[2];
                bhh[0] = Bh[nr * SM_STRIDE + w0];
                bhh[1] = Bh[nr * SM_STRIDE + w0 + 4];
                bmm[0] = Bm[nr * SM_STRIDE + w0];
                bmm[1] = Bm[nr * SM_STRIDE + w0 + 4];
#pragma unroll
                for (int mf = 0; mf < 2; mf++) {
                    mma_bf16(acc[mf][nf], ahh[mf], bhh);
                    mma_bf16(acc[mf][nf], amm[mf], bhh);
                    mma_bf16(acc[mf][nf], ahh[mf], bmm);
                }
            }
        }
        __syncthreads();
    }

    // epilogue: bias add, store logits
#pragma unroll
    for (int mf = 0; mf < 2; mf++) {
        const int row = bm + wm * 32 + mf * 16 + grp;
#pragma unroll
        for (int nf = 0; nf < 8; nf++) {
            const int col = bn + wn * 64 + nf * 8 + tg * 2;
            const float b0 = __ldg(&bias[col]);
            const float b1 = __ldg(&bias[col + 1]);
            float2 v0 = make_float2(acc[mf][nf][0] + b0, acc[mf][nf][1] + b1);
            float2 v1 = make_float2(acc[mf][nf][2] + b0, acc[mf][nf][3] + b1);
            *(float2*)&g_logits[(size_t)row * N_COLS + col]       = v0;
            *(float2*)&g_logits[(size_t)(row + 8) * N_COLS + col] = v1;
        }
    }
}

// ---------------------------------------------------------------------------
// Kernel 2: per-row argmax (top-2 + exact fp32 recheck on near-ties) +
// softmax accumulation + codebook gather.  (unchanged from R4, proven)
// ---------------------------------------------------------------------------
#define RPB   32
#define BATCH 8

__global__ __launch_bounds__(256)
void reduce_kernel(const float* __restrict__ codebook,   // [640, 128]
                   const float* __restrict__ x,          // [65536, 512]
                   const float* __restrict__ bias,       // [640]
                   float* __restrict__ out)              // [65536, 256]
{
    __shared__ __align__(16) float sl[BATCH][N_COLS];
    __shared__ float sm[BATCH][2];
    __shared__ float sinv[BATCH][2];
    __shared__ int   sk[BATCH][2];
    __shared__ unsigned int shist[N_COLS];

    const int tid  = threadIdx.x;
    const int lane = tid & 31;
    const int warp = tid >> 5;

    for (int i = tid; i < N_COLS; i += 256) shist[i] = 0u;

    const int c0 = tid, c1 = tid + 256, c2 = tid + 512;
    float accp0 = 0.0f, accp1 = 0.0f, accp2 = 0.0f;
    const bool c1g0 = (c1 < NUM_VARS);

    const int row0 = blockIdx.x * RPB;

    for (int rb = 0; rb < RPB; rb += BATCH) {
        const int rbase = row0 + rb;
        __syncthreads();

        const float4* src = (const float4*)(g_logits + (size_t)rbase * N_COLS);
        float4* dst = (float4*)&sl[0][0];
#pragma unroll
        for (int i = 0; i < (BATCH * N_COLS) / 4 / 256; i++)
            dst[tid + i * 256] = src[tid + i * 256];
        __syncthreads();

        if (warp < BATCH) {
            const int r = warp;
            const int row = rbase + r;
#pragma unroll
            for (int g = 0; g < GROUPS; g++) {
                const float* lp = &sl[r][g * NUM_VARS];
                float bv = NEG_HUGE, sv = NEG_HUGE;
                int   bi = 0,        si = 0;
#pragma unroll
                for (int j = 0; j < NUM_VARS / 32; j++) {
                    int idx = lane + 32 * j;
                    float v = lp[idx];
                    if (v > bv)      { sv = bv; si = bi; bv = v; bi = idx; }
                    else if (v > sv) { sv = v; si = idx; }
                }
#pragma unroll
                for (int s = 16; s > 0; s >>= 1) {
                    float ob = __shfl_xor_sync(0xffffffffu, bv, s);
                    int   oi = __shfl_xor_sync(0xffffffffu, bi, s);
                    float os = __shfl_xor_sync(0xffffffffu, sv, s);
                    int   oj = __shfl_xor_sync(0xffffffffu, si, s);
                    if (ob > bv || (ob == bv && oi < bi)) {
                        if (os > bv || (os == bv && oj < bi)) { sv = os; si = oj; }
                        else                                  { sv = bv; si = bi; }
                        bv = ob; bi = oi;
                    } else {
                        if (ob > sv || (ob == sv && oi < si)) { sv = ob; si = oi; }
                    }
                }
                if (bv - sv < GAP_THR) {
                    const float* xr = x + (size_t)row * K_DIM;
                    const float* w1 = g_wt + (size_t)(g * NUM_VARS + bi) * K_DIM;
                    const float* w2 = g_wt + (size_t)(g * NUM_VARS + si) * K_DIM;
                    float d1 = 0.0f, d2 = 0.0f;
#pragma unroll
                    for (int k = lane; k < K_DIM; k += 32) {
                        float xv = xr[k];
                        d1 = fmaf(xv, w1[k], d1);
                        d2 = fmaf(xv, w2[k], d2);
                    }
#pragma unroll
                    for (int s = 16; s > 0; s >>= 1) {
                        d1 += __shfl_xor_sync(0xffffffffu, d1, s);
                        d2 += __shfl_xor_sync(0xffffffffu, d2, s);
                    }
                    d1 += bias[g * NUM_VARS + bi];
                    d2 += bias[g * NUM_VARS + si];
                    if (d2 > d1 || (d2 == d1 && si < bi)) bi = si;
                }
                float se = 0.0f;
#pragma unroll
                for (int j = 0; j < NUM_VARS / 32; j++)
                    se += __expf(lp[lane + 32 * j] - bv);
#pragma unroll
                for (int s = 16; s > 0; s >>= 1)
                    se += __shfl_xor_sync(0xffffffffu, se, s);
                if (lane == 0) {
                    sm[r][g]   = bv;
                    sinv[r][g] = 1.0f / se;
                    sk[r][g]   = bi;
                    atomicAdd(&shist[g * NUM_VARS + bi], 1u);
                }
            }
        }
        __syncthreads();

#pragma unroll
        for (int r = 0; r < BATCH; r++) {
            float m0 = sm[r][0], m1 = sm[r][1];
            float i0 = sinv[r][0], i1 = sinv[r][1];
            accp0 += __expf(sl[r][c0] - m0) * i0;
            if (c1g0) accp1 += __expf(sl[r][c1] - m0) * i0;
            else      accp1 += __expf(sl[r][c1] - m1) * i1;
            if (c2 < N_COLS) accp2 += __expf(sl[r][c2] - m1) * i1;
        }

#pragma unroll
        for (int r = 0; r < BATCH; r++) {
            const int row = rbase + r;
            const int c   = tid;
            const int g   = c >> 7;
            const int k   = sk[r][g];
            out[(size_t)row * 256 + c] =
                __ldg(&codebook[(size_t)(g * NUM_VARS + k) * CB_DIM + (c & 127)]);
        }
    }

    __syncthreads();
    atomicAdd(&g_probsum[c0], accp0);
    atomicAdd(&g_probsum[c1], accp1);
    if (c2 < N_COLS) atomicAdd(&g_probsum[c2], accp2);
    for (int i = tid; i < N_COLS; i += 256)
        if (shist[i]) atomicAdd(&g_counts[i], shist[i]);
}

// ---------------------------------------------------------------------------
// Kernel 3: perplexities (tiny)
// ---------------------------------------------------------------------------
__global__ void finalize_kernel(float* __restrict__ out2)
{
    __shared__ float red_h[N_COLS];
    __shared__ float red_s[N_COLS];
    __shared__ float gh[2], gs[2];
    const int tid = threadIdx.x;
    const float invN = 1.0f / (float)M_ROWS;

    if (tid < N_COLS) {
        float ph = (float)g_counts[tid] * invN;
        float ps = g_probsum[tid] * invN;
        red_h[tid] = ph * logf(ph + EPSV);
        red_s[tid] = ps * logf(ps + EPSV);
    }
    __syncthreads();

    if (tid < 64) {
        const int g = tid >> 5, lane = tid & 31;
        float sh = 0.0f, ss = 0.0f;
#pragma unroll
        for (int j = 0; j < NUM_VARS / 32; j++) {
            sh += red_h[g * NUM_VARS + lane + 32 * j];
            ss += red_s[g * NUM_VARS + lane + 32 * j];
        }
#pragma unroll
        for (int s = 16; s > 0; s >>= 1) {
            sh += __shfl_xor_sync(0xffffffffu, sh, s);
            ss += __shfl_xor_sync(0xffffffffu, ss, s);
        }
        if (lane == 0) { gh[g] = expf(-sh); gs[g] = expf(-ss); }
    }
    __syncthreads();

    if (tid == 0) {
        out2[0] = gh[0] + gh[1];
        out2[1] = gs[0] + gs[1];
    }
}

// ---------------------------------------------------------------------------
extern "C" void kernel_launch(void* const* d_in, const int* in_sizes, int n_in,
                              void* d_out, int out_size)
{
    const float* x   = (const float*)d_in[0];   // [16,4096,512]
    const float* W   = (const float*)d_in[1];   // [512,640]
    const float* b   = (const float*)d_in[2];   // [640]
    const float* cb  = (const float*)d_in[3];   // [640,128]
    float*       out = (float*)d_out;

    cudaFuncSetAttribute(gemm_bf16x3_kernel,
                         cudaFuncAttributeMaxDynamicSharedMemorySize, GEMM_SMEM);

    zero_kernel<<<1, N_COLS>>>();

    dim3 wg(K_DIM / 64, N_COLS / 64);           // (8, 10)
    wprep_kernel<<<wg, 256>>>(W);

    dim3 gg(N_COLS / 128, M_ROWS / 128);        // (5, 512)
    gemm_bf16x3_kernel<<<gg, 256, GEMM_SMEM>>>(x, b);

    reduce_kernel<<<M_ROWS / RPB, 256>>>(cb, x, b, out);

    finalize_kernel<<<1, N_COLS>>>(out + out_size - 2);
}

// round 6
// speedup vs baseline: 2.7358x; 1.6733x over previous
#include <cuda_runtime.h>
#include <cstdint>

#define M_ROWS 65536
#define N_COLS 640
#define K_DIM  512
#define GROUPS 2
#define NUM_VARS 320
#define CB_DIM 128
#define EPSV 1e-7f
#define NEG_HUGE -3.402823466e38f
#define GAP_THR 0.25f

// ---------------------------------------------------------------------------
// Static device scratch (no cudaMalloc allowed)
// ---------------------------------------------------------------------------
__device__ float        g_logits[(size_t)M_ROWS * N_COLS];
__device__ float        g_wt[(size_t)N_COLS * K_DIM];           // W^T fp32 (exact recheck)
__device__ uint32_t     g_wth[(size_t)N_COLS * (K_DIM / 2)];    // W^T fp16x2, k-pair packed
__device__ float        g_probsum[N_COLS];
__device__ unsigned int g_counts[N_COLS];

// ---------------------------------------------------------------------------
// Helpers (baseline sm_103 PTX only: cp.async, mma.sync fp16)
// ---------------------------------------------------------------------------
__device__ __forceinline__ uint32_t smem_to_u32(const void* p) {
    uint32_t a;
    asm("{ .reg .u64 t; cvta.to.shared.u64 t, %1; cvt.u32.u64 %0, t; }" : "=r"(a) : "l"(p));
    return a;
}
__device__ __forceinline__ void cp16(uint32_t s, const void* g) {
    asm volatile("cp.async.cg.shared.global [%0], [%1], 16;" :: "r"(s), "l"(g) : "memory");
}
__device__ __forceinline__ void cp_commit() {
    asm volatile("cp.async.commit_group;" ::: "memory");
}
// pack two consecutive-k floats into fp16x2 (low half = even k)
__device__ __forceinline__ uint32_t h2pack(float e, float o) {
    uint32_t h;
    asm("cvt.rn.f16x2.f32 %0, %1, %2;" : "=r"(h) : "f"(o), "f"(e));
    return h;
}
__device__ __forceinline__ void mma_fp16(float* c, const uint32_t* a, const uint32_t* b) {
    asm volatile(
        "mma.sync.aligned.m16n8k16.row.col.f32.f16.f16.f32 "
        "{%0,%1,%2,%3}, {%4,%5,%6,%7}, {%8,%9}, {%0,%1,%2,%3};"
        : "+f"(c[0]), "+f"(c[1]), "+f"(c[2]), "+f"(c[3])
        : "r"(a[0]), "r"(a[1]), "r"(a[2]), "r"(a[3]), "r"(b[0]), "r"(b[1]));
}
#define STS128U(a0, a1, a2, a3, saddr) \
    asm volatile("st.shared.v4.b32 [%0], {%1, %2, %3, %4};" :: "r"(saddr), "r"(a0), "r"(a1), "r"(a2), "r"(a3) : "memory")

// ---------------------------------------------------------------------------
// Kernel 0a: zero accumulators (graph replayed -> reset every call)
// ---------------------------------------------------------------------------
__global__ void zero_kernel() {
    int i = threadIdx.x;
    if (i < N_COLS) { g_probsum[i] = 0.0f; g_counts[i] = 0u; }
}

// ---------------------------------------------------------------------------
// Kernel 0b: W prep — fp32 transpose (recheck) + fp16 pack, k-pair packed
// ---------------------------------------------------------------------------
__global__ __launch_bounds__(256)
void wprep_kernel(const float* __restrict__ W) {
    __shared__ float t[64][65];
    const int kt = blockIdx.x * 64, nt = blockIdx.y * 64;
    const int tid = threadIdx.x;

    for (int i = tid; i < 64 * 64; i += 256) {
        int k = i >> 6, n = i & 63;
        t[k][n] = W[(size_t)(kt + k) * N_COLS + nt + n];
    }
    __syncthreads();
    for (int i = tid; i < 64 * 64; i += 256) {
        int n = i >> 6, k = i & 63;
        g_wt[(size_t)(nt + n) * K_DIM + kt + k] = t[k][n];
    }
    for (int i = tid; i < 64 * 32; i += 256) {
        int n = i >> 5, w = i & 31;
        g_wth[(size_t)(nt + n) * (K_DIM / 2) + (kt >> 1) + w] =
            h2pack(t[2 * w][n], t[2 * w + 1][n]);
    }
}

// ---------------------------------------------------------------------------
// Kernel 1: single-pass fp16 GEMM via mma.sync.m16n8k16 (fp32 accumulate).
// CTA 128x128, 8 warps (warp tile 32x64), K-chunks of 32 fp32 (=16 words),
// double-buffered: B via cp.async from pre-packed g_wth, A converted
// in-register -> STS.  Smem rows padded to 20 words -> conflict-free LDS.
// ---------------------------------------------------------------------------
#define SM_STRIDE 20
#define TILE_B    (128 * SM_STRIDE * 4)   // 10240 bytes per tile
#define A_OFF     0
#define B_OFF     TILE_B
#define STAGE_B   (2 * TILE_B)            // 20480
#define GEMM_SMEM (2 * STAGE_B)           // 40960
#define NCHUNK 16

__global__ __launch_bounds__(256, 2)
void gemm_fp16_kernel(const float* __restrict__ A,     // x [65536, 512]
                      const float* __restrict__ bias)  // b [640]
{
    extern __shared__ char smem[];
    const int tid  = threadIdx.x;
    const int wid  = tid >> 5;
    const int lane = tid & 31;
    const int bm   = blockIdx.y * 128;
    const int bn   = blockIdx.x * 128;
    const int wm   = wid & 3;      // M-warp 0..3 -> rows wm*32..+32
    const int wn   = wid >> 2;     // N-warp 0..1 -> cols wn*64..+64
    const int grp  = lane >> 2;    // 0..7
    const int tg   = lane & 3;     // 0..3
    const uint32_t sb = smem_to_u32(smem);

    float acc[2][8][4];
#pragma unroll
    for (int mf = 0; mf < 2; mf++)
#pragma unroll
        for (int nf = 0; nf < 8; nf++)
#pragma unroll
            for (int r = 0; r < 4; r++) acc[mf][nf][r] = 0.0f;

    // loader mapping: thread -> (row 0..127, half 0/1 of the 32-float chunk)
    const int lr = tid >> 1;
    const int lh = tid & 1;
    const float4*   Ag = (const float4*)(A + (size_t)(bm + lr) * K_DIM + lh * 16);
    const uint32_t* Bg = g_wth + (size_t)(bn + lr) * (K_DIM / 2) + lh * 8;
    const uint32_t  base = (uint32_t)(lr * SM_STRIDE + lh * 8) * 4;

    float4 av[4];

#define STS_A(stg) do {                                                          \
        uint32_t _w[8];                                                          \
        _Pragma("unroll")                                                        \
        for (int q = 0; q < 4; q++) {                                            \
            _w[2*q]   = h2pack(av[q].x, av[q].y);                                \
            _w[2*q+1] = h2pack(av[q].z, av[q].w);                                \
        }                                                                        \
        uint32_t _ba = sb + (uint32_t)(stg) * STAGE_B + base + A_OFF;            \
        STS128U(_w[0], _w[1], _w[2], _w[3], _ba);                                \
        STS128U(_w[4], _w[5], _w[6], _w[7], _ba + 16);                           \
    } while (0)

#define CP_B(c, stg) do {                                                        \
        uint32_t _bb = sb + (uint32_t)(stg) * STAGE_B + base + B_OFF;            \
        const uint32_t* _g = Bg + (c) * 16;                                      \
        cp16(_bb, _g);  cp16(_bb + 16, _g + 4);                                  \
        cp_commit();                                                             \
    } while (0)

    // prologue: chunk0 -> stage0; A(1) into regs
#pragma unroll
    for (int q = 0; q < 4; q++) av[q] = Ag[q];
    CP_B(0, 0);
    STS_A(0);
#pragma unroll
    for (int q = 0; q < 4; q++) av[q] = Ag[8 + q];

    for (int c = 0; c < NCHUNK; c++) {
        const int st = c & 1;
        if (c + 1 < NCHUNK) {
            STS_A(st ^ 1);
            if (c + 2 < NCHUNK) {
#pragma unroll
                for (int q = 0; q < 4; q++) av[q] = Ag[(c + 2) * 8 + q];
            }
            CP_B(c + 1, st ^ 1);
            asm volatile("cp.async.wait_group 1;" ::: "memory");
        } else {
            asm volatile("cp.async.wait_group 0;" ::: "memory");
        }
        __syncthreads();

        const uint32_t* Ah = (const uint32_t*)(smem + (size_t)st * STAGE_B + A_OFF);
        const uint32_t* Bh = (const uint32_t*)(smem + (size_t)st * STAGE_B + B_OFF);

#pragma unroll
        for (int ks = 0; ks < 2; ks++) {
            const int w0 = ks * 8 + tg;
            uint32_t af[2][4];
#pragma unroll
            for (int mf = 0; mf < 2; mf++) {
                const int r = wm * 32 + mf * 16 + grp;
                af[mf][0] = Ah[r * SM_STRIDE + w0];
                af[mf][1] = Ah[(r + 8) * SM_STRIDE + w0];
                af[mf][2] = Ah[r * SM_STRIDE + w0 + 4];
                af[mf][3] = Ah[(r + 8) * SM_STRIDE + w0 + 4];
            }
#pragma unroll
            for (int nf = 0; nf < 8; nf++) {
                const int nr = wn * 64 + nf * 8 + grp;
                uint32_t bf[2];
                bf[0] = Bh[nr * SM_STRIDE + w0];
                bf[1] = Bh[nr * SM_STRIDE + w0 + 4];
#pragma unroll
                for (int mf = 0; mf < 2; mf++)
                    mma_fp16(acc[mf][nf], af[mf], bf);
            }
        }
        __syncthreads();
    }

    // epilogue: bias add, store logits
#pragma unroll
    for (int mf = 0; mf < 2; mf++) {
        const int row = bm + wm * 32 + mf * 16 + grp;
#pragma unroll
        for (int nf = 0; nf < 8; nf++) {
            const int col = bn + wn * 64 + nf * 8 + tg * 2;
            const float b0 = __ldg(&bias[col]);
            const float b1 = __ldg(&bias[col + 1]);
            float2 v0 = make_float2(acc[mf][nf][0] + b0, acc[mf][nf][1] + b1);
            float2 v1 = make_float2(acc[mf][nf][2] + b0, acc[mf][nf][3] + b1);
            *(float2*)&g_logits[(size_t)row * N_COLS + col]       = v0;
            *(float2*)&g_logits[(size_t)(row + 8) * N_COLS + col] = v1;
        }
    }
}

// ---------------------------------------------------------------------------
// Kernel 2: per-row argmax (approx top-2 + exact fp32 recheck of ALL
// candidates within GAP_THR of the approx max) + softmax + codebook gather.
// ---------------------------------------------------------------------------
#define RPB   32
#define BATCH 8

__global__ __launch_bounds__(256)
void reduce_kernel(const float* __restrict__ codebook,   // [640, 128]
                   const float* __restrict__ x,          // [65536, 512]
                   const float* __restrict__ bias,       // [640]
                   float* __restrict__ out)              // [65536, 256]
{
    __shared__ __align__(16) float sl[BATCH][N_COLS];
    __shared__ float sm[BATCH][2];
    __shared__ float sinv[BATCH][2];
    __shared__ int   sk[BATCH][2];
    __shared__ unsigned int shist[N_COLS];

    const int tid  = threadIdx.x;
    const int lane = tid & 31;
    const int warp = tid >> 5;

    for (int i = tid; i < N_COLS; i += 256) shist[i] = 0u;

    const int c0 = tid, c1 = tid + 256, c2 = tid + 512;
    float accp0 = 0.0f, accp1 = 0.0f, accp2 = 0.0f;
    const bool c1g0 = (c1 < NUM_VARS);

    const int row0 = blockIdx.x * RPB;

    for (int rb = 0; rb < RPB; rb += BATCH) {
        const int rbase = row0 + rb;
        __syncthreads();

        const float4* src = (const float4*)(g_logits + (size_t)rbase * N_COLS);
        float4* dst = (float4*)&sl[0][0];
#pragma unroll
        for (int i = 0; i < (BATCH * N_COLS) / 4 / 256; i++)
            dst[tid + i * 256] = src[tid + i * 256];
        __syncthreads();

        if (warp < BATCH) {
            const int r = warp;
            const int row = rbase + r;
#pragma unroll
            for (int g = 0; g < GROUPS; g++) {
                const float* lp = &sl[r][g * NUM_VARS];
                // approx top-2 (value + index, first-max tiebreak)
                float bv = NEG_HUGE, sv = NEG_HUGE;
                int   bi = 0,        si = 0;
#pragma unroll
                for (int j = 0; j < NUM_VARS / 32; j++) {
                    int idx = lane + 32 * j;
                    float v = lp[idx];
                    if (v > bv)      { sv = bv; si = bi; bv = v; bi = idx; }
                    else if (v > sv) { sv = v; si = idx; }
                }
#pragma unroll
                for (int s = 16; s > 0; s >>= 1) {
                    float ob = __shfl_xor_sync(0xffffffffu, bv, s);
                    int   oi = __shfl_xor_sync(0xffffffffu, bi, s);
                    float os = __shfl_xor_sync(0xffffffffu, sv, s);
                    int   oj = __shfl_xor_sync(0xffffffffu, si, s);
                    if (ob > bv || (ob == bv && oi < bi)) {
                        if (os > bv || (os == bv && oj < bi)) { sv = os; si = oj; }
                        else                                  { sv = bv; si = bi; }
                        bv = ob; bi = oi;
                    } else {
                        if (ob > sv || (ob == sv && oi < si)) { sv = ob; si = oi; }
                    }
                }
                // near-tie -> exact fp32 recheck of ALL candidates within THR
                if (bv - sv < GAP_THR) {
                    const float* xr = x + (size_t)row * K_DIM;
                    float bestd = NEG_HUGE; int besti = NUM_VARS;
                    const float cutoff = bv - GAP_THR;
#pragma unroll
                    for (int j = 0; j < NUM_VARS / 32; j++) {
                        int idx = lane + 32 * j;
                        unsigned mask = __ballot_sync(0xffffffffu, lp[idx] >= cutoff);
                        while (mask) {
                            int srcl = __ffs(mask) - 1;
                            mask &= mask - 1;
                            int ci = srcl + 32 * j;
                            const float* wv = g_wt + (size_t)(g * NUM_VARS + ci) * K_DIM;
                            float d = 0.0f;
#pragma unroll
                            for (int k = lane; k < K_DIM; k += 32)
                                d = fmaf(xr[k], wv[k], d);
#pragma unroll
                            for (int s = 16; s > 0; s >>= 1)
                                d += __shfl_xor_sync(0xffffffffu, d, s);
                            d += bias[g * NUM_VARS + ci];
                            if (d > bestd || (d == bestd && ci < besti)) {
                                bestd = d; besti = ci;
                            }
                        }
                    }
                    bi = besti;
                }
                // softmax denominator on approx logits (consistent with accum)
                float se = 0.0f;
#pragma unroll
                for (int j = 0; j < NUM_VARS / 32; j++)
                    se += __expf(lp[lane + 32 * j] - bv);
#pragma unroll
                for (int s = 16; s > 0; s >>= 1)
                    se += __shfl_xor_sync(0xffffffffu, se, s);
                if (lane == 0) {
                    sm[r][g]   = bv;
                    sinv[r][g] = 1.0f / se;
                    sk[r][g]   = bi;
                    atomicAdd(&shist[g * NUM_VARS + bi], 1u);
                }
            }
        }
        __syncthreads();

#pragma unroll
        for (int r = 0; r < BATCH; r++) {
            float m0 = sm[r][0], m1 = sm[r][1];
            float i0 = sinv[r][0], i1 = sinv[r][1];
            accp0 += __expf(sl[r][c0] - m0) * i0;
            if (c1g0) accp1 += __expf(sl[r][c1] - m0) * i0;
            else      accp1 += __expf(sl[r][c1] - m1) * i1;
            if (c2 < N_COLS) accp2 += __expf(sl[r][c2] - m1) * i1;
        }

#pragma unroll
        for (int r = 0; r < BATCH; r++) {
            const int row = rbase + r;
            const int c   = tid;
            const int g   = c >> 7;
            const int k   = sk[r][g];
            out[(size_t)row * 256 + c] =
                __ldg(&codebook[(size_t)(g * NUM_VARS + k) * CB_DIM + (c & 127)]);
        }
    }

    __syncthreads();
    atomicAdd(&g_probsum[c0], accp0);
    atomicAdd(&g_probsum[c1], accp1);
    if (c2 < N_COLS) atomicAdd(&g_probsum[c2], accp2);
    for (int i = tid; i < N_COLS; i += 256)
        if (shist[i]) atomicAdd(&g_counts[i], shist[i]);
}

// ---------------------------------------------------------------------------
// Kernel 3: perplexities (tiny)
// ---------------------------------------------------------------------------
__global__ void finalize_kernel(float* __restrict__ out2)
{
    __shared__ float red_h[N_COLS];
    __shared__ float red_s[N_COLS];
    __shared__ float gh[2], gs[2];
    const int tid = threadIdx.x;
    const float invN = 1.0f / (float)M_ROWS;

    if (tid < N_COLS) {
        float ph = (float)g_counts[tid] * invN;
        float ps = g_probsum[tid] * invN;
        red_h[tid] = ph * logf(ph + EPSV);
        red_s[tid] = ps * logf(ps + EPSV);
    }
    __syncthreads();

    if (tid < 64) {
        const int g = tid >> 5, lane = tid & 31;
        float sh = 0.0f, ss = 0.0f;
#pragma unroll
        for (int j = 0; j < NUM_VARS / 32; j++) {
            sh += red_h[g * NUM_VARS + lane + 32 * j];
            ss += red_s[g * NUM_VARS + lane + 32 * j];
        }
#pragma unroll
        for (int s = 16; s > 0; s >>= 1) {
            sh += __shfl_xor_sync(0xffffffffu, sh, s);
            ss += __shfl_xor_sync(0xffffffffu, ss, s);
        }
        if (lane == 0) { gh[g] = expf(-sh); gs[g] = expf(-ss); }
    }
    __syncthreads();

    if (tid == 0) {
        out2[0] = gh[0] + gh[1];
        out2[1] = gs[0] + gs[1];
    }
}

// ---------------------------------------------------------------------------
extern "C" void kernel_launch(void* const* d_in, const int* in_sizes, int n_in,
                              void* d_out, int out_size)
{
    const float* x   = (const float*)d_in[0];   // [16,4096,512]
    const float* W   = (const float*)d_in[1];   // [512,640]
    const float* b   = (const float*)d_in[2];   // [640]
    const float* cb  = (const float*)d_in[3];   // [640,128]
    float*       out = (float*)d_out;

    cudaFuncSetAttribute(gemm_fp16_kernel,
                         cudaFuncAttributeMaxDynamicSharedMemorySize, GEMM_SMEM);

    zero_kernel<<<1, N_COLS>>>();

    dim3 wg(K_DIM / 64, N_COLS / 64);           // (8, 10)
    wprep_kernel<<<wg, 256>>>(W);

    dim3 gg(N_COLS / 128, M_ROWS / 128);        // (5, 512)
    gemm_fp16_kernel<<<gg, 256, GEMM_SMEM>>>(x, b);

    reduce_kernel<<<M_ROWS / RPB, 256>>>(cb, x, b, out);

    finalize_kernel<<<1, N_COLS>>>(out + out_size - 2);
}